// round 9
// baseline (speedup 1.0000x reference)
#include <cuda_runtime.h>
#include <cuda_bf16.h>
#include <cstdint>

// Fixed shape: B=1, N=768, C_IN=C_OUT=16, R=8
#define NPTS   768
#define NTHR   256
#define NKS    48           // total ksteps (K=768 / 16)
#define KHALF  384          // b's per K-half
#define NCTAS  768          // 384 m-tiles x 2 K-halves

typedef unsigned int u32;

// B fragments in mma-register order, built by conv_prep:
//   g_bfragH[ks][lane] = {b00, b01, b10, b11} (uint4); identical for all CTAs.
__device__ uint4 g_bfragH[NKS * 32];
__device__ uint4 g_bfragL[NKS * 32];

__device__ __forceinline__ u32 pack_bf16x2(float lo, float hi) {
    u32 d;
    asm("cvt.rn.bf16x2.f32 %0, %1, %2;" : "=r"(d) : "f"(hi), "f"(lo));
    return d;
}
__device__ __forceinline__ float ex2f(float x) {
    float e;
    asm("ex2.approx.f32 %0, %1;" : "=f"(e) : "f"(x));
    return e;
}
__device__ __forceinline__ float sqrt_apx(float x) {
    float s;
    asm("sqrt.approx.f32 %0, %1;" : "=f"(s) : "f"(x));
    return s;
}
// D(16x8,f32) += A(16x16,row,bf16) * B(16x8,col,bf16)
__device__ __forceinline__ void mma16816(float& c0, float& c1, float& c2, float& c3,
                                         u32 a0, u32 a1, u32 a2, u32 a3,
                                         u32 b0, u32 b1) {
    asm("mma.sync.aligned.m16n8k16.row.col.f32.bf16.bf16.f32 "
        "{%0,%1,%2,%3}, {%4,%5,%6,%7}, {%8,%9}, {%0,%1,%2,%3};"
        : "+f"(c0), "+f"(c1), "+f"(c2), "+f"(c3)
        : "r"(a0), "r"(a1), "r"(a2), "r"(a3), "r"(b0), "r"(b1));
}

// ---------------------------------------------------------------------------
// Prep: blocks 0-5 build B fragments; blocks 6-53 zero `out` (atomic target).
// ---------------------------------------------------------------------------
__global__ void __launch_bounds__(NTHR) conv_prep(const float* __restrict__ feat,
                                                  float* __restrict__ out)
{
    if (blockIdx.x >= 6) {
        out[(blockIdx.x - 6) * NTHR + threadIdx.x] = 0.f;
        return;
    }
    const int idx  = blockIdx.x * NTHR + threadIdx.x;     // 0..1535
    const int ks   = idx >> 5;
    const int lane = idx & 31;
    const int g    = lane >> 2;
    const int k0   = ks * 16 + (lane & 3) * 2;

    float f[8];
    #pragma unroll
    for (int q = 0; q < 2; q++) {                         // q=0: col g, q=1: col g+8
        const int j = g + q * 8;
        f[q * 4 + 0] = __ldg(&feat[(k0)     * 16 + j]);
        f[q * 4 + 1] = __ldg(&feat[(k0 + 1) * 16 + j]);
        f[q * 4 + 2] = __ldg(&feat[(k0 + 8) * 16 + j]);
        f[q * 4 + 3] = __ldg(&feat[(k0 + 9) * 16 + j]);
    }
    float h[8], l[8];
    #pragma unroll
    for (int q = 0; q < 8; q++) {
        h[q] = __bfloat162float(__float2bfloat16(f[q]));
        l[q] = f[q] - h[q];
    }
    uint4 BH, BL;
    BH.x = pack_bf16x2(h[0], h[1]);  BH.y = pack_bf16x2(h[2], h[3]);
    BH.z = pack_bf16x2(h[4], h[5]);  BH.w = pack_bf16x2(h[6], h[7]);
    BL.x = pack_bf16x2(l[0], l[1]);  BL.y = pack_bf16x2(l[2], l[3]);
    BL.z = pack_bf16x2(l[4], l[5]);  BL.w = pack_bf16x2(l[6], l[7]);
    g_bfragH[ks * 32 + lane] = BH;
    g_bfragL[ks * 32 + lane] = BL;
}

// ---------------------------------------------------------------------------
// Main: CTA = (m-tile of 16 rows, K-half).  mtile = bx>>1, khalf = bx&1.
//   Prologue computes distances only for its 384-b half.
//   Warp w covers local K slice [w*48, w*48+48) in 3 ksteps of 16.
//   Epilogue: 8-warp reduce, W-contract, atomicAdd into zeroed `out`
//   (exactly 2 commutative fp32 adds per element -> bitwise deterministic).
// ---------------------------------------------------------------------------
__global__ void __launch_bounds__(NTHR, 3) conv_main(
    const float* __restrict__ geom,    // [768,3]
    const float* __restrict__ W,       // [8,16,16]
    const float* __restrict__ mu,      // [8]
    const float* __restrict__ gamma,   // [8]
    float scale,
    float* __restrict__ out)           // [768,16]
{
    __shared__ float sD[2 * KHALF];    // distances d[a_local][b_local]
    __shared__ float sRed[8 * 256];    // per-warp C tiles [w][row][col]
    __shared__ float sG[256];          // reduced G [row][col]

    const int tid   = threadIdx.x;
    const int lane  = tid & 31;
    const int warp  = tid >> 5;
    const int mtile = blockIdx.x >> 1;
    const int khalf = blockIdx.x & 1;
    const int a0    = mtile * 2;
    const int bbase = khalf * KHALF;

    // ---- distances: 768 values, 3 per thread ----
    {
        const float g0x = __ldg(&geom[a0 * 3]),       g0y = __ldg(&geom[a0 * 3 + 1]),
                    g0z = __ldg(&geom[a0 * 3 + 2]);
        const float g1x = __ldg(&geom[a0 * 3 + 3]),   g1y = __ldg(&geom[a0 * 3 + 4]),
                    g1z = __ldg(&geom[a0 * 3 + 5]);
        #pragma unroll
        for (int q = 0; q < 3; q++) {
            const int v    = tid + q * NTHR;          // 0..767
            const int aL   = v >= KHALF;
            const int bloc = v - aL * KHALF;
            const int b    = bbase + bloc;
            const float bx = __ldg(&geom[b * 3]);
            const float by = __ldg(&geom[b * 3 + 1]);
            const float bz = __ldg(&geom[b * 3 + 2]);
            const float dx = bx - (aL ? g1x : g0x);
            const float dy = by - (aL ? g1y : g0y);
            const float dz = bz - (aL ? g1z : g0z);
            float d2 = fmaf(dx, dx, 1e-9f);
            d2 = fmaf(dy, dy, d2);
            d2 = fmaf(dz, dz, d2);
            sD[v] = sqrt_apx(d2);
        }
    }
    __syncthreads();

    // PDL: prep's B-fragment writes AND out-zeroing must be visible past here.
    asm volatile("griddepcontrol.wait;" ::: "memory");

    const int g = lane >> 2;           // fragment group = r
    const int c = (lane & 3) * 2;

    // RBF consts for this lane's r=g:  pw = -(kr*d + mr)^2
    const float kr = sqrt_apx(__ldg(gamma + g) * 1.44269504088896f);
    const float mr = -__ldg(mu + g) * kr;

    float accA[8], accB[8];            // dual sets: even/odd ksteps
    #pragma unroll
    for (int k = 0; k < 8; k++) { accA[k] = 0.f; accB[k] = 0.f; }

    const int kb0 = warp * 48 + c;     // local k offset
    const uint4* bHp = g_bfragH + (khalf * 24 + warp * 3) * 32 + lane;
    const uint4* bLp = g_bfragL + (khalf * 24 + warp * 3) * 32 + lane;

    // ---- prefetch B frags for kstep 0 (coalesced LDG.128 x2) ----
    uint4 BH[2], BL[2];
    BH[0] = bHp[0];
    BL[0] = bLp[0];

    #pragma unroll
    for (int s = 0; s < 3; s++) {
        const int kb  = kb0 + s * 16;
        const int cur = s & 1;
        const int nxt = cur ^ 1;

        if (s < 2) {                   // prefetch next kstep
            BH[nxt] = bHp[(s + 1) * 32];
            BL[nxt] = bLp[(s + 1) * 32];
        }

        // ---- A fragments (rbf hi/lo) from smem distances ----
        const float2 d00 = *(const float2*)&sD[kb];            // row g   , cols c,c+1
        const float2 d01 = *(const float2*)&sD[kb + 8];        // row g   , cols c+8,c+9
        const float2 d10 = *(const float2*)&sD[KHALF + kb];    // row g+8
        const float2 d11 = *(const float2*)&sD[KHALF + kb + 8];

        float v;
        v = fmaf(d00.x, kr, mr); const float e00x = ex2f(v * (-v));
        v = fmaf(d00.y, kr, mr); const float e00y = ex2f(v * (-v));
        v = fmaf(d10.x, kr, mr); const float e10x = ex2f(v * (-v));
        v = fmaf(d10.y, kr, mr); const float e10y = ex2f(v * (-v));
        v = fmaf(d01.x, kr, mr); const float e01x = ex2f(v * (-v));
        v = fmaf(d01.y, kr, mr); const float e01y = ex2f(v * (-v));
        v = fmaf(d11.x, kr, mr); const float e11x = ex2f(v * (-v));
        v = fmaf(d11.y, kr, mr); const float e11y = ex2f(v * (-v));

        const u32 ah0 = pack_bf16x2(e00x, e00y);
        const u32 ah1 = pack_bf16x2(e10x, e10y);
        const u32 ah2 = pack_bf16x2(e01x, e01y);
        const u32 ah3 = pack_bf16x2(e11x, e11y);

        const u32 al0 = pack_bf16x2(e00x - __uint_as_float(ah0 << 16),
                                    e00y - __uint_as_float(ah0 & 0xFFFF0000u));
        const u32 al1 = pack_bf16x2(e10x - __uint_as_float(ah1 << 16),
                                    e10y - __uint_as_float(ah1 & 0xFFFF0000u));
        const u32 al2 = pack_bf16x2(e01x - __uint_as_float(ah2 << 16),
                                    e01y - __uint_as_float(ah2 & 0xFFFF0000u));
        const u32 al3 = pack_bf16x2(e11x - __uint_as_float(ah3 << 16),
                                    e11y - __uint_as_float(ah3 & 0xFFFF0000u));

        float* acc = (s & 1) ? accB : accA;   // compile-time (fully unrolled)
        const uint4 bh = BH[cur], bl = BL[cur];
        mma16816(acc[0], acc[1], acc[2], acc[3], ah0, ah1, ah2, ah3, bh.x, bh.y);
        mma16816(acc[4], acc[5], acc[6], acc[7], ah0, ah1, ah2, ah3, bh.z, bh.w);
        mma16816(acc[0], acc[1], acc[2], acc[3], al0, al1, al2, al3, bh.x, bh.y);
        mma16816(acc[4], acc[5], acc[6], acc[7], al0, al1, al2, al3, bh.z, bh.w);
        mma16816(acc[0], acc[1], acc[2], acc[3], ah0, ah1, ah2, ah3, bl.x, bl.y);
        mma16816(acc[4], acc[5], acc[6], acc[7], ah0, ah1, ah2, ah3, bl.z, bl.w);
    }

    // ---- merge dual sets ----
    #pragma unroll
    for (int k = 0; k < 8; k++) accA[k] += accB[k];

    // ---- stash per-warp C tile: sRed[w][row][col] ----
    {
        float* rb = sRed + warp * 256;
        *(float2*)&rb[g * 16 + c]            = make_float2(accA[0], accA[1]);
        *(float2*)&rb[(g + 8) * 16 + c]      = make_float2(accA[2], accA[3]);
        *(float2*)&rb[g * 16 + 8 + c]        = make_float2(accA[4], accA[5]);
        *(float2*)&rb[(g + 8) * 16 + 8 + c]  = make_float2(accA[6], accA[7]);
    }
    __syncthreads();

    // ---- reduce over 8 warps ----
    {
        float s = 0.f;
        #pragma unroll
        for (int w = 0; w < 8; w++) s += sRed[w * 256 + tid];
        sG[tid] = s;
    }
    __syncthreads();

    // ---- W contraction + atomic combine of the two K-halves ----
    {
        const int r2 = tid & 7;
        const int i  = (tid >> 3) & 15;
        const int aL = tid >> 7;
        const float* gp = sG + (aL * 8 + r2) * 16;
        const float4* wp = (const float4*)W + r2 * 64 + i * 4;
        float a = 0.f;
        #pragma unroll
        for (int q = 0; q < 4; q++) {
            const float4 g4 = *(const float4*)(gp + q * 4);
            const float4 w4 = __ldg(wp + q);
            a = fmaf(w4.x, g4.x, a);
            a = fmaf(w4.y, g4.y, a);
            a = fmaf(w4.z, g4.z, a);
            a = fmaf(w4.w, g4.w, a);
        }
        a += __shfl_xor_sync(0xffffffffu, a, 1);
        a += __shfl_xor_sync(0xffffffffu, a, 2);
        a += __shfl_xor_sync(0xffffffffu, a, 4);
        // 2 commutative fp32 adds onto 0.0 -> bitwise deterministic.
        if (r2 == 0) atomicAdd(&out[(a0 + aL) * 16 + i], a * scale);
    }
}

// ---------------------------------------------------------------------------
extern "C" void kernel_launch(void* const* d_in, const int* in_sizes, int n_in,
                              void* d_out, int out_size)
{
    const float* feat  = (const float*)d_in[0];   // [1,768,16]
    const float* geom  = (const float*)d_in[1];   // [1,768,3]
    const float* W     = (const float*)d_in[2];   // [8,16,16]
    const float* mu    = (const float*)d_in[3];   // [8]
    const float* gamma = (const float*)d_in[4];   // [8]
    float* out = (float*)d_out;

    const int n_norm = in_sizes[1] / 3;
    const float scale = 1.0f / sqrtf((float)n_norm);

    conv_prep<<<54, NTHR>>>(feat, out);           // frags + zero out

    // PDL launch: overlap conv_main's launch + distance prologue with prep.
    cudaLaunchConfig_t cfg = {};
    cfg.gridDim  = dim3(NCTAS);
    cfg.blockDim = dim3(NTHR);
    cfg.dynamicSmemBytes = 0;
    cfg.stream = 0;
    cudaLaunchAttribute at[1];
    at[0].id = cudaLaunchAttributeProgrammaticStreamSerialization;
    at[0].val.programmaticStreamSerializationAllowed = 1;
    cfg.attrs = at;
    cfg.numAttrs = 1;
    cudaLaunchKernelEx(&cfg, conv_main, geom, W, mu, gamma, scale, out);
}

// round 10
// speedup vs baseline: 1.4048x; 1.4048x over previous
#include <cuda_runtime.h>
#include <cuda_bf16.h>
#include <cstdint>

// Fixed shape: B=1, N=768, C_IN=C_OUT=16, R=8
#define NPTS   768
#define NTILES 384          // M-tiles of 16 rows (2 a's x 8 r); one CTA each
#define NTHR   256
#define NKS    48           // total ksteps (K=768 / 16)

typedef unsigned int u32;

// B fragments in mma-register order, built by conv_prep:
//   g_bfragH[ks][lane] = {b00, b01, b10, b11} (uint4); identical for all CTAs.
__device__ uint4 g_bfragH[NKS * 32];
__device__ uint4 g_bfragL[NKS * 32];

__device__ __forceinline__ u32 pack_bf16x2(float lo, float hi) {
    u32 d;
    asm("cvt.rn.bf16x2.f32 %0, %1, %2;" : "=r"(d) : "f"(hi), "f"(lo));
    return d;
}
__device__ __forceinline__ float ex2f(float x) {
    float e;
    asm("ex2.approx.f32 %0, %1;" : "=f"(e) : "f"(x));
    return e;
}
__device__ __forceinline__ float sqrt_apx(float x) {
    float s;
    asm("sqrt.approx.f32 %0, %1;" : "=f"(s) : "f"(x));
    return s;
}
// D(16x8,f32) += A(16x16,row,bf16) * B(16x8,col,bf16)
__device__ __forceinline__ void mma16816(float& c0, float& c1, float& c2, float& c3,
                                         u32 a0, u32 a1, u32 a2, u32 a3,
                                         u32 b0, u32 b1) {
    asm("mma.sync.aligned.m16n8k16.row.col.f32.bf16.bf16.f32 "
        "{%0,%1,%2,%3}, {%4,%5,%6,%7}, {%8,%9}, {%0,%1,%2,%3};"
        : "+f"(c0), "+f"(c1), "+f"(c2), "+f"(c3)
        : "r"(a0), "r"(a1), "r"(a2), "r"(a3), "r"(b0), "r"(b1));
}

// ---------------------------------------------------------------------------
// Prep: build hi/lo bf16 B fragments directly in mma-fragment order.
// ---------------------------------------------------------------------------
__global__ void __launch_bounds__(NTHR) conv_prep(const float* __restrict__ feat)
{
    const int idx  = blockIdx.x * NTHR + threadIdx.x;     // 0..1535
    const int ks   = idx >> 5;
    const int lane = idx & 31;
    const int g    = lane >> 2;
    const int k0   = ks * 16 + (lane & 3) * 2;

    float f[8];
    #pragma unroll
    for (int q = 0; q < 2; q++) {                         // q=0: col g, q=1: col g+8
        const int j = g + q * 8;
        f[q * 4 + 0] = __ldg(&feat[(k0)     * 16 + j]);
        f[q * 4 + 1] = __ldg(&feat[(k0 + 1) * 16 + j]);
        f[q * 4 + 2] = __ldg(&feat[(k0 + 8) * 16 + j]);
        f[q * 4 + 3] = __ldg(&feat[(k0 + 9) * 16 + j]);
    }
    float h[8], l[8];
    #pragma unroll
    for (int q = 0; q < 8; q++) {
        h[q] = __bfloat162float(__float2bfloat16(f[q]));
        l[q] = f[q] - h[q];
    }
    uint4 BH, BL;
    BH.x = pack_bf16x2(h[0], h[1]);  BH.y = pack_bf16x2(h[2], h[3]);
    BH.z = pack_bf16x2(h[4], h[5]);  BH.w = pack_bf16x2(h[6], h[7]);
    BL.x = pack_bf16x2(l[0], l[1]);  BL.y = pack_bf16x2(l[2], l[3]);
    BL.z = pack_bf16x2(l[4], l[5]);  BL.w = pack_bf16x2(l[6], l[7]);
    g_bfragH[ks * 32 + lane] = BH;
    g_bfragL[ks * 32 + lane] = BL;
}

// ---------------------------------------------------------------------------
// Main (R8 topology, reg-dieted for 4 CTAs/SM = 32 warps):
//   CTA = M-tile of 16 rows (2 a's x 8 r). Warp w covers K [w*96, w*96+96)
//   in 6 ksteps. Single accumulator set, no double-buffer (regs <= 64;
//   latency covered by residency). PDL overlap with conv_prep.
// ---------------------------------------------------------------------------
__global__ void __launch_bounds__(NTHR, 4) conv_main(
    const float* __restrict__ geom,    // [768,3]
    const float* __restrict__ W,       // [8,16,16]
    const float* __restrict__ mu,      // [8]
    const float* __restrict__ gamma,   // [8]
    float scale,
    float* __restrict__ out)           // [768,16]
{
    __shared__ float sD[2 * NPTS];     // distances d[a_local][b]
    __shared__ float sRed[8 * 256];    // per-warp C tiles [w][row][col]
    __shared__ float sG[256];          // reduced G [row][col]

    const int tid  = threadIdx.x;
    const int lane = tid & 31;
    const int warp = tid >> 5;
    const int a0   = blockIdx.x * 2;

    // ---- distances: 1536 values, 6 per thread ----
    {
        const float g0x = __ldg(&geom[a0 * 3]),       g0y = __ldg(&geom[a0 * 3 + 1]),
                    g0z = __ldg(&geom[a0 * 3 + 2]);
        const float g1x = __ldg(&geom[a0 * 3 + 3]),   g1y = __ldg(&geom[a0 * 3 + 4]),
                    g1z = __ldg(&geom[a0 * 3 + 5]);
        #pragma unroll
        for (int q = 0; q < 6; q++) {
            const int v  = tid + q * NTHR;            // 0..1535
            const int aL = v >= NPTS;
            const int b  = v - aL * NPTS;
            const float bx = __ldg(&geom[b * 3]);
            const float by = __ldg(&geom[b * 3 + 1]);
            const float bz = __ldg(&geom[b * 3 + 2]);
            const float dx = bx - (aL ? g1x : g0x);
            const float dy = by - (aL ? g1y : g0y);
            const float dz = bz - (aL ? g1z : g0z);
            float d2 = fmaf(dx, dx, 1e-9f);
            d2 = fmaf(dy, dy, d2);
            d2 = fmaf(dz, dz, d2);
            sD[v] = sqrt_apx(d2);
        }
    }
    __syncthreads();

    // PDL: prep's writes to g_bfragH/L must be visible past this point.
    asm volatile("griddepcontrol.wait;" ::: "memory");

    const int g = lane >> 2;           // fragment group = r
    const int c = (lane & 3) * 2;

    // RBF consts for this lane's r=g:  pw = -(kr*d + mr)^2
    const float kr = sqrt_apx(__ldg(gamma + g) * 1.44269504088896f);
    const float mr = -__ldg(mu + g) * kr;

    float acc[8];
    #pragma unroll
    for (int k = 0; k < 8; k++) acc[k] = 0.f;

    const int kb0 = warp * 96 + c;
    const uint4* bHp = g_bfragH + (warp * 6) * 32 + lane;
    const uint4* bLp = g_bfragL + (warp * 6) * 32 + lane;

    #pragma unroll
    for (int s = 0; s < 6; s++) {
        const int kb = kb0 + s * 16;

        // B frags: 2 coalesced LDG.128 (L1-resident; latency covered by occ)
        const uint4 bh = bHp[s * 32];
        const uint4 bl = bLp[s * 32];

        // ---- A fragments (rbf hi/lo) from smem distances ----
        const float2 d00 = *(const float2*)&sD[kb];            // row g   , cols c,c+1
        const float2 d01 = *(const float2*)&sD[kb + 8];        // row g   , cols c+8,c+9
        const float2 d10 = *(const float2*)&sD[NPTS + kb];     // row g+8
        const float2 d11 = *(const float2*)&sD[NPTS + kb + 8];

        float v;
        v = fmaf(d00.x, kr, mr); const float e00x = ex2f(v * (-v));
        v = fmaf(d00.y, kr, mr); const float e00y = ex2f(v * (-v));
        v = fmaf(d10.x, kr, mr); const float e10x = ex2f(v * (-v));
        v = fmaf(d10.y, kr, mr); const float e10y = ex2f(v * (-v));
        v = fmaf(d01.x, kr, mr); const float e01x = ex2f(v * (-v));
        v = fmaf(d01.y, kr, mr); const float e01y = ex2f(v * (-v));
        v = fmaf(d11.x, kr, mr); const float e11x = ex2f(v * (-v));
        v = fmaf(d11.y, kr, mr); const float e11y = ex2f(v * (-v));

        const u32 ah0 = pack_bf16x2(e00x, e00y);
        const u32 ah1 = pack_bf16x2(e10x, e10y);
        const u32 ah2 = pack_bf16x2(e01x, e01y);
        const u32 ah3 = pack_bf16x2(e11x, e11y);

        const u32 al0 = pack_bf16x2(e00x - __uint_as_float(ah0 << 16),
                                    e00y - __uint_as_float(ah0 & 0xFFFF0000u));
        const u32 al1 = pack_bf16x2(e10x - __uint_as_float(ah1 << 16),
                                    e10y - __uint_as_float(ah1 & 0xFFFF0000u));
        const u32 al2 = pack_bf16x2(e01x - __uint_as_float(ah2 << 16),
                                    e01y - __uint_as_float(ah2 & 0xFFFF0000u));
        const u32 al3 = pack_bf16x2(e11x - __uint_as_float(ah3 << 16),
                                    e11y - __uint_as_float(ah3 & 0xFFFF0000u));

        mma16816(acc[0], acc[1], acc[2], acc[3], ah0, ah1, ah2, ah3, bh.x, bh.y);
        mma16816(acc[4], acc[5], acc[6], acc[7], ah0, ah1, ah2, ah3, bh.z, bh.w);
        mma16816(acc[0], acc[1], acc[2], acc[3], al0, al1, al2, al3, bh.x, bh.y);
        mma16816(acc[4], acc[5], acc[6], acc[7], al0, al1, al2, al3, bh.z, bh.w);
        mma16816(acc[0], acc[1], acc[2], acc[3], ah0, ah1, ah2, ah3, bl.x, bl.y);
        mma16816(acc[4], acc[5], acc[6], acc[7], ah0, ah1, ah2, ah3, bl.z, bl.w);
    }

    // ---- stash per-warp C tile: sRed[w][row][col] ----
    {
        float* rb = sRed + warp * 256;
        *(float2*)&rb[g * 16 + c]            = make_float2(acc[0], acc[1]);
        *(float2*)&rb[(g + 8) * 16 + c]      = make_float2(acc[2], acc[3]);
        *(float2*)&rb[g * 16 + 8 + c]        = make_float2(acc[4], acc[5]);
        *(float2*)&rb[(g + 8) * 16 + 8 + c]  = make_float2(acc[6], acc[7]);
    }
    __syncthreads();

    // ---- reduce over 8 warps ----
    {
        float s = 0.f;
        #pragma unroll
        for (int w = 0; w < 8; w++) s += sRed[w * 256 + tid];
        sG[tid] = s;
    }
    __syncthreads();

    // ---- W contraction: thread = (a_local, i, r); reduce r via shfl ----
    {
        const int r2 = tid & 7;
        const int i  = (tid >> 3) & 15;
        const int aL = tid >> 7;
        const float* gp = sG + (aL * 8 + r2) * 16;
        const float4* wp = (const float4*)W + r2 * 64 + i * 4;
        float a = 0.f;
        #pragma unroll
        for (int q = 0; q < 4; q++) {
            const float4 g4 = *(const float4*)(gp + q * 4);
            const float4 w4 = __ldg(wp + q);
            a = fmaf(w4.x, g4.x, a);
            a = fmaf(w4.y, g4.y, a);
            a = fmaf(w4.z, g4.z, a);
            a = fmaf(w4.w, g4.w, a);
        }
        a += __shfl_xor_sync(0xffffffffu, a, 1);
        a += __shfl_xor_sync(0xffffffffu, a, 2);
        a += __shfl_xor_sync(0xffffffffu, a, 4);
        if (r2 == 0) out[(a0 + aL) * 16 + i] = a * scale;
    }
}

// ---------------------------------------------------------------------------
extern "C" void kernel_launch(void* const* d_in, const int* in_sizes, int n_in,
                              void* d_out, int out_size)
{
    const float* feat  = (const float*)d_in[0];   // [1,768,16]
    const float* geom  = (const float*)d_in[1];   // [1,768,3]
    const float* W     = (const float*)d_in[2];   // [8,16,16]
    const float* mu    = (const float*)d_in[3];   // [8]
    const float* gamma = (const float*)d_in[4];   // [8]
    float* out = (float*)d_out;

    const int n_norm = in_sizes[1] / 3;
    const float scale = 1.0f / sqrtf((float)n_norm);

    conv_prep<<<6, NTHR>>>(feat);

    // PDL launch: overlap conv_main's launch + distance prologue with prep.
    cudaLaunchConfig_t cfg = {};
    cfg.gridDim  = dim3(NTILES);
    cfg.blockDim = dim3(NTHR);
    cfg.dynamicSmemBytes = 0;
    cfg.stream = 0;
    cudaLaunchAttribute at[1];
    at[0].id = cudaLaunchAttributeProgrammaticStreamSerialization;
    at[0].val.programmaticStreamSerializationAllowed = 1;
    cfg.attrs = at;
    cfg.numAttrs = 1;
    cudaLaunchKernelEx(&cfg, conv_main, geom, W, mu, gamma, scale, out);
}